// round 4
// baseline (speedup 1.0000x reference)
#include <cuda_runtime.h>

#define NODE_F 8
#define EDGE_F 2
#define HID 16
#define NMAX 100000
#define EMAX 1600000
#define ESTEPS 4   // edges per block = 64 * ESTEPS

// ---- scratch (__device__ globals per allocation-free rule) ----
__device__ alignas(16) float d_xA[NMAX * NODE_F];
__device__ alignas(16) float d_xB[NMAX * NODE_F];
__device__ alignas(16) float d_ea[EMAX * EDGE_F];
__device__ alignas(16) float d_p[NMAX * HID];     // A_l . x[n]  (64B row, line-aligned)
__device__ alignas(16) float d_q[NMAX * HID];     // B_l . x[n]
__device__ alignas(16) float d_agg[NMAX * EDGE_F];   // zero-init, self-cleaning
__device__ float d_g;
__device__ float d_eacc[EDGE_F];   // zero-init, self-cleaning
__device__ float d_nacc[NODE_F];   // zero-init, self-cleaning
__device__ float d_ebias[2][HID];  // b1_e + g*W1_e[g-row], double buffered
__device__ float d_nbias[2][HID];
__device__ unsigned d_count;       // zero-init, self-cleaning

// ---------------------------------------------------------------------------
// layer-0 p/q precompute from external x; block 0 also folds layer-0 biases.
__global__ __launch_bounds__(256)
void pre_kernel(const float* __restrict__ x,
                const float* __restrict__ A, const float* __restrict__ B,
                const float* __restrict__ g_in,
                const float* __restrict__ eW1r0, const float* __restrict__ eb1,
                const float* __restrict__ nW1r0, const float* __restrict__ nb1,
                float* __restrict__ ebias0, float* __restrict__ nbias0, int N)
{
    if (blockIdx.x == 0 && threadIdx.x < 32) {
        int t = threadIdx.x;
        float g = g_in[0];
        if (t < HID) {
            ebias0[t] = eb1[t] + g * eW1r0[t];
            nbias0[t] = nb1[t] + g * nW1r0[t];
        }
        if (t == 0) d_g = g;
    }
    __shared__ float sA[NODE_F * HID], sB[NODE_F * HID];
    for (int i = threadIdx.x; i < NODE_F * HID; i += blockDim.x) { sA[i] = A[i]; sB[i] = B[i]; }
    __syncthreads();
    for (int n = blockIdx.x * blockDim.x + threadIdx.x; n < N; n += gridDim.x * blockDim.x) {
        float xv[NODE_F];
        *reinterpret_cast<float4*>(xv)     = *reinterpret_cast<const float4*>(x + (size_t)n * NODE_F);
        *reinterpret_cast<float4*>(xv + 4) = *reinterpret_cast<const float4*>(x + (size_t)n * NODE_F + 4);
        float pv[HID], qv[HID];
        #pragma unroll
        for (int j = 0; j < HID; j++) { pv[j] = 0.f; qv[j] = 0.f; }
        #pragma unroll
        for (int k = 0; k < NODE_F; k++) {
            float v = xv[k];
            #pragma unroll
            for (int j = 0; j < HID; j++) {
                pv[j] = fmaf(v, sA[k * HID + j], pv[j]);
                qv[j] = fmaf(v, sB[k * HID + j], qv[j]);
            }
        }
        float4* pd = reinterpret_cast<float4*>(d_p + (size_t)n * HID);
        float4* qd = reinterpret_cast<float4*>(d_q + (size_t)n * HID);
        #pragma unroll
        for (int v = 0; v < 4; v++) {
            pd[v] = reinterpret_cast<float4*>(pv)[v];
            qd[v] = reinterpret_cast<float4*>(qv)[v];
        }
    }
}

// ---------------------------------------------------------------------------
// Edge block, 4 lanes per edge, software-pipelined over ESTEPS:
//   phase 1: load all indices (coalesced, independent)
//   phase 2: issue all p/q gathers + ea loads (8 x LDG.128 outstanding)
//   phase 3: compute, cross-lane reduce, scatter
template<bool WRITE_EA, bool REDUCE>
__global__ __launch_bounds__(256)
void edge_kernel(const int* __restrict__ ei, const float* __restrict__ ea,
                 const float* __restrict__ C, const float* __restrict__ W2,
                 const float* __restrict__ b2, const float* __restrict__ ebias,
                 float* __restrict__ ea_out, int E)
{
    __shared__ float sC[2 * HID], sW2[HID * 2], sEb[HID];
    __shared__ float sred[2][8];
    int tx = threadIdx.x;
    if (tx < 32)       sC[tx] = C[tx];
    else if (tx < 64)  sW2[tx - 32] = W2[tx - 32];
    else if (tx < 80)  sEb[tx - 64] = ebias[tx - 64];
    __syncthreads();

    const float B20 = __ldg(&b2[0]);
    const float B21 = __ldg(&b2[1]);

    const int sub   = tx & 3;
    const int group = tx >> 2;          // 0..63
    const int j0    = sub * 4;
    const int ebase = blockIdx.x * (64 * ESTEPS) + group;

    // phase 1: indices
    int r[ESTEPS], c[ESTEPS];
    #pragma unroll
    for (int s = 0; s < ESTEPS; s++) {
        int e = ebase + s * 64;
        int ee = (e < E) ? e : 0;
        r[s] = __ldg(ei + ee);
        c[s] = __ldg(ei + E + ee);
    }
    // phase 2: gathers + edge attrs, all in flight
    float4 pv[ESTEPS], qv[ESTEPS];
    float2 eav[ESTEPS];
    #pragma unroll
    for (int s = 0; s < ESTEPS; s++) {
        pv[s] = *reinterpret_cast<const float4*>(d_p + (size_t)r[s] * HID + j0);
        qv[s] = *reinterpret_cast<const float4*>(d_q + (size_t)c[s] * HID + j0);
        int e = ebase + s * 64;
        eav[s] = (e < E) ? *reinterpret_cast<const float2*>(ea + (size_t)e * EDGE_F)
                         : make_float2(0.f, 0.f);
    }

    float acc0 = 0.f, acc1 = 0.f;
    // phase 3: compute + scatter
    #pragma unroll
    for (int s = 0; s < ESTEPS; s++) {
        int e = ebase + s * 64;
        float o0 = 0.f, o1 = 0.f;
        float hp[4] = {pv[s].x, pv[s].y, pv[s].z, pv[s].w};
        float hq[4] = {qv[s].x, qv[s].y, qv[s].z, qv[s].w};
        #pragma unroll
        for (int k = 0; k < 4; k++) {
            float h = sEb[j0 + k] + hp[k] + hq[k];
            h = fmaf(eav[s].x, sC[j0 + k], h);
            h = fmaf(eav[s].y, sC[HID + j0 + k], h);
            h = fmaxf(h, 0.f);
            o0 = fmaf(h, sW2[2 * (j0 + k)],     o0);
            o1 = fmaf(h, sW2[2 * (j0 + k) + 1], o1);
        }
        o0 += __shfl_xor_sync(0xffffffffu, o0, 1);
        o1 += __shfl_xor_sync(0xffffffffu, o1, 1);
        o0 += __shfl_xor_sync(0xffffffffu, o0, 2);
        o1 += __shfl_xor_sync(0xffffffffu, o1, 2);

        if (sub == 0 && e < E) {
            o0 += B20; o1 += B21;
            if (WRITE_EA)
                *reinterpret_cast<float2*>(ea_out + (size_t)e * EDGE_F) = make_float2(o0, o1);
            float* dst = &d_agg[(size_t)r[s] * EDGE_F];
            asm volatile("red.global.add.v2.f32 [%0], {%1, %2};"
                         :: "l"(dst), "f"(o0), "f"(o1) : "memory");
            if (REDUCE) { acc0 += o0; acc1 += o1; }
        }
    }

    if (REDUCE) {
        #pragma unroll
        for (int off = 16; off; off >>= 1) {
            acc0 += __shfl_down_sync(0xffffffffu, acc0, off);
            acc1 += __shfl_down_sync(0xffffffffu, acc1, off);
        }
        int warp = tx >> 5, lane = tx & 31;
        if (lane == 0) { sred[0][warp] = acc0; sred[1][warp] = acc1; }
        __syncthreads();
        if (tx == 0) {
            float t0 = 0.f, t1 = 0.f;
            #pragma unroll
            for (int w = 0; w < 8; w++) { t0 += sred[0][w]; t1 += sred[1][w]; }
            atomicAdd(&d_eacc[0], t0);
            atomicAdd(&d_eacc[1], t1);
        }
    }
}

// ---------------------------------------------------------------------------
// Node block, grid-stride (grid sized to exactly fill the chip, no wave tail):
// n_in = [g, x, agg] -> MLP(11->16 relu ->8).
// FUSE: next-layer p/q, node-sum reduction, last block runs the global MLP.
template<bool FUSE>
__global__ __launch_bounds__(256)
void node_kernel(const float* __restrict__ x,
                 const float* __restrict__ W1,      // rows 1..10 (160 floats)
                 const float* __restrict__ nbias,
                 const float* __restrict__ W2, const float* __restrict__ b2,
                 float* __restrict__ x_out,
                 const float* __restrict__ An, const float* __restrict__ Bn,
                 const float* __restrict__ gW1, const float* __restrict__ gb1,
                 const float* __restrict__ gW2, const float* __restrict__ gb2,
                 const float* __restrict__ eW1r0n, const float* __restrict__ eb1n,
                 const float* __restrict__ nW1r0n, const float* __restrict__ nb1n,
                 float* __restrict__ ebias_out, float* __restrict__ nbias_out,
                 float invE, float invN, int N)
{
    __shared__ float sW1[10 * HID], sNb[HID], sW2n[HID * NODE_F], sB2[NODE_F];
    __shared__ float sA[NODE_F * HID], sBm[NODE_F * HID];
    __shared__ float sred[NODE_F][8];
    __shared__ bool  isLast;
    int tx = threadIdx.x;

    for (int i = tx; i < 10 * HID; i += 256) sW1[i] = W1[i];
    for (int i = tx; i < HID * NODE_F; i += 256) sW2n[i] = W2[i];
    if (tx < HID)    sNb[tx] = nbias[tx];
    if (tx < NODE_F) sB2[tx] = b2[tx];
    if (FUSE) {
        for (int i = tx; i < NODE_F * HID; i += 256) { sA[i] = An[i]; sBm[i] = Bn[i]; }
    }
    __syncthreads();

    float nsum[NODE_F];
    #pragma unroll
    for (int k = 0; k < NODE_F; k++) nsum[k] = 0.f;

    const int stride = gridDim.x * blockDim.x;
    for (int n = blockIdx.x * blockDim.x + tx; n < N; n += stride) {
        float xv[NODE_F];
        *reinterpret_cast<float4*>(xv)     = *reinterpret_cast<const float4*>(x + (size_t)n * NODE_F);
        *reinterpret_cast<float4*>(xv + 4) = *reinterpret_cast<const float4*>(x + (size_t)n * NODE_F + 4);
        float2 av = *reinterpret_cast<float2*>(&d_agg[(size_t)n * EDGE_F]);
        *reinterpret_cast<float2*>(&d_agg[(size_t)n * EDGE_F]) = make_float2(0.f, 0.f); // self-clean

        float h[HID];
        #pragma unroll
        for (int j = 0; j < HID; j++) h[j] = sNb[j];
        #pragma unroll
        for (int i = 0; i < NODE_F; i++) {
            float v = xv[i];
            #pragma unroll
            for (int j = 0; j < HID; j++) h[j] = fmaf(v, sW1[i * HID + j], h[j]);
        }
        #pragma unroll
        for (int j = 0; j < HID; j++) {
            h[j] = fmaf(av.x, sW1[8 * HID + j], h[j]);
            h[j] = fmaf(av.y, sW1[9 * HID + j], h[j]);
        }
        float out[NODE_F];
        #pragma unroll
        for (int k = 0; k < NODE_F; k++) out[k] = sB2[k];
        #pragma unroll
        for (int j = 0; j < HID; j++) {
            float hv = fmaxf(h[j], 0.f);
            #pragma unroll
            for (int k = 0; k < NODE_F; k++)
                out[k] = fmaf(hv, sW2n[j * NODE_F + k], out[k]);
        }
        *reinterpret_cast<float4*>(x_out + (size_t)n * NODE_F)     = *reinterpret_cast<float4*>(out);
        *reinterpret_cast<float4*>(x_out + (size_t)n * NODE_F + 4) = *reinterpret_cast<float4*>(out + 4);

        if (FUSE) {
            #pragma unroll
            for (int k = 0; k < NODE_F; k++) nsum[k] += out[k];
            float pv[HID], qv[HID];
            #pragma unroll
            for (int j = 0; j < HID; j++) { pv[j] = 0.f; qv[j] = 0.f; }
            #pragma unroll
            for (int k = 0; k < NODE_F; k++) {
                float v = out[k];
                #pragma unroll
                for (int j = 0; j < HID; j++) {
                    pv[j] = fmaf(v, sA[k * HID + j], pv[j]);
                    qv[j] = fmaf(v, sBm[k * HID + j], qv[j]);
                }
            }
            float4* pd = reinterpret_cast<float4*>(d_p + (size_t)n * HID);
            float4* qd = reinterpret_cast<float4*>(d_q + (size_t)n * HID);
            #pragma unroll
            for (int v = 0; v < 4; v++) {
                pd[v] = reinterpret_cast<float4*>(pv)[v];
                qd[v] = reinterpret_cast<float4*>(qv)[v];
            }
        }
    }

    if (FUSE) {
        int warp = tx >> 5, lane = tx & 31;
        #pragma unroll
        for (int k = 0; k < NODE_F; k++) {
            float s = nsum[k];
            #pragma unroll
            for (int off = 16; off; off >>= 1)
                s += __shfl_down_sync(0xffffffffu, s, off);
            if (lane == 0) sred[k][warp] = s;
        }
        __syncthreads();
        if (tx < NODE_F) {
            float t = 0.f;
            #pragma unroll
            for (int w = 0; w < 8; w++) t += sred[tx][w];
            atomicAdd(&d_nacc[tx], t);
            __threadfence();
        }
        __syncthreads();
        if (tx == 0) {
            unsigned t = atomicAdd(&d_count, 1u);
            isLast = (t == gridDim.x - 1);
        }
        __syncthreads();

        if (isLast) {
            __threadfence();
            if (tx < 32) {
                float gv = d_g;
                float h = 0.f;
                if (tx < HID) {
                    h = gb1[tx];
                    #pragma unroll
                    for (int i = 0; i < NODE_F; i++)
                        h = fmaf(d_nacc[i] * invN, gW1[i * HID + tx], h);
                    h = fmaf(d_eacc[0] * invE, gW1[8 * HID + tx], h);
                    h = fmaf(d_eacc[1] * invE, gW1[9 * HID + tx], h);
                    h = fmaf(gv, gW1[10 * HID + tx], h);
                    h = fmaxf(h, 0.f) * gW2[tx];
                }
                #pragma unroll
                for (int off = 16; off; off >>= 1)
                    h += __shfl_down_sync(0xffffffffu, h, off);
                float gn = __shfl_sync(0xffffffffu, h, 0) + gb2[0];
                if (tx == 0) d_g = gn;
                if (tx < HID) {
                    ebias_out[tx] = eb1n[tx] + gn * eW1r0n[tx];
                    nbias_out[tx] = nb1n[tx] + gn * nW1r0n[tx];
                }
                if (tx < NODE_F) d_nacc[tx] = 0.f;   // self-clean
                if (tx < EDGE_F) d_eacc[tx] = 0.f;
                if (tx == 0)     d_count = 0u;
            }
        }
    }
}

// ---------------------------------------------------------------------------
extern "C" void kernel_launch(void* const* d_in, const int* in_sizes, int n_in,
                              void* d_out, int out_size)
{
    const float* x0  = (const float*)d_in[0];
    const int*   ei  = (const int*)  d_in[1];
    const float* ea0 = (const float*)d_in[2];
    const float* g0  = (const float*)d_in[3];
    const float* eW1 = (const float*)d_in[4];
    const float* eb1 = (const float*)d_in[5];
    const float* eW2 = (const float*)d_in[6];
    const float* eb2 = (const float*)d_in[7];
    const float* nW1 = (const float*)d_in[8];
    const float* nb1 = (const float*)d_in[9];
    const float* nW2 = (const float*)d_in[10];
    const float* nb2 = (const float*)d_in[11];
    const float* gW1 = (const float*)d_in[12];
    const float* gb1 = (const float*)d_in[13];
    const float* gW2 = (const float*)d_in[14];
    const float* gb2 = (const float*)d_in[15];

    const int N = in_sizes[0] / NODE_F;
    const int E = in_sizes[2] / EDGE_F;
    float* out = (float*)d_out;

    float *xA, *xB, *ea, *pEb, *pNb;
    cudaGetSymbolAddress((void**)&xA,  d_xA);
    cudaGetSymbolAddress((void**)&xB,  d_xB);
    cudaGetSymbolAddress((void**)&ea,  d_ea);
    cudaGetSymbolAddress((void**)&pEb, d_ebias);
    cudaGetSymbolAddress((void**)&pNb, d_nbias);

    const float invE = 1.0f / (float)E;
    const float invN = 1.0f / (float)N;

    const int EW1S = 19 * HID, NW1S = 11 * HID, GW1S = 11 * HID;

    pre_kernel<<<296, 256>>>(x0, eW1 + HID, eW1 + 9 * HID,
                             g0, eW1, eb1, nW1, nb1, pEb, pNb, N);

    const float* xin[3]  = {x0, xA, xB};
    float*       xout[3] = {xA, xB, out};
    const float* eain[3] = {ea0, ea, ea};

    const int EPB = 64 * ESTEPS;
    const int eblocks = (E + EPB - 1) / EPB;
    const int nblocks = 296;   // 2 full waves on 148 SMs, grid-stride inside

    for (int l = 0; l < 3; l++) {
        const float* C    = eW1 + l * EW1S + 17 * HID;
        const float* W2e  = eW2 + l * HID * EDGE_F;
        const float* b2e  = eb2 + l * EDGE_F;
        const float* eb_l = pEb + (l & 1) * HID;

        if (l < 2)
            edge_kernel<true, true><<<eblocks, 256>>>(ei, eain[l], C, W2e, b2e, eb_l, ea, E);
        else
            edge_kernel<false, false><<<eblocks, 256>>>(ei, eain[l], C, W2e, b2e, eb_l, ea, E);

        const float* W1n  = nW1 + l * NW1S + HID;
        const float* nb_l = pNb + (l & 1) * HID;
        const float* W2n  = nW2 + l * HID * NODE_F;
        const float* b2n  = nb2 + l * NODE_F;

        if (l < 2) {
            node_kernel<true><<<nblocks, 256>>>(
                xin[l], W1n, nb_l, W2n, b2n, xout[l],
                eW1 + (l + 1) * EW1S + HID, eW1 + (l + 1) * EW1S + 9 * HID,
                gW1 + l * GW1S, gb1 + l * HID, gW2 + l * HID, gb2 + l,
                eW1 + (l + 1) * EW1S, eb1 + (l + 1) * HID,
                nW1 + (l + 1) * NW1S, nb1 + (l + 1) * HID,
                pEb + ((l + 1) & 1) * HID, pNb + ((l + 1) & 1) * HID,
                invE, invN, N);
        } else {
            node_kernel<false><<<nblocks, 256>>>(
                xin[l], W1n, nb_l, W2n, b2n, xout[l],
                nullptr, nullptr, nullptr, nullptr, nullptr, nullptr,
                nullptr, nullptr, nullptr, nullptr, nullptr, nullptr,
                invE, invN, N);
        }
    }
}

// round 5
// speedup vs baseline: 2.1810x; 2.1810x over previous
#include <cuda_runtime.h>

#define NODE_F 8
#define EDGE_F 2
#define HID 16
#define NMAX 100000
#define EMAX 1600000
#define ESTEPS 2   // edges per block = 64 * ESTEPS

// ---- scratch (__device__ globals per allocation-free rule) ----
__device__ alignas(16) float d_xA[NMAX * NODE_F];
__device__ alignas(16) float d_xB[NMAX * NODE_F];
__device__ alignas(16) float d_ea[EMAX * EDGE_F];
__device__ alignas(16) float d_p[NMAX * HID];     // A_l . x[n]  (64B row, line-aligned)
__device__ alignas(16) float d_q[NMAX * HID];     // B_l . x[n]
__device__ alignas(16) float d_agg[NMAX * EDGE_F];   // zero-init, self-cleaning
__device__ float d_g;
__device__ float d_eacc[EDGE_F];   // zero-init, self-cleaning
__device__ float d_nacc[NODE_F];   // zero-init, self-cleaning
__device__ float d_ebias[2][HID];  // b1_e + g*W1_e[g-row], double buffered
__device__ float d_nbias[2][HID];
__device__ unsigned d_count;       // zero-init, self-cleaning

// ---------------------------------------------------------------------------
// layer-0 p/q precompute from external x; block 0 also folds layer-0 biases.
__global__ __launch_bounds__(256)
void pre_kernel(const float* __restrict__ x,
                const float* __restrict__ A, const float* __restrict__ B,
                const float* __restrict__ g_in,
                const float* __restrict__ eW1r0, const float* __restrict__ eb1,
                const float* __restrict__ nW1r0, const float* __restrict__ nb1,
                float* __restrict__ ebias0, float* __restrict__ nbias0, int N)
{
    if (blockIdx.x == 0 && threadIdx.x < 32) {
        int t = threadIdx.x;
        float g = g_in[0];
        if (t < HID) {
            ebias0[t] = eb1[t] + g * eW1r0[t];
            nbias0[t] = nb1[t] + g * nW1r0[t];
        }
        if (t == 0) d_g = g;
    }
    __shared__ float sA[NODE_F * HID], sB[NODE_F * HID];
    for (int i = threadIdx.x; i < NODE_F * HID; i += blockDim.x) { sA[i] = A[i]; sB[i] = B[i]; }
    __syncthreads();
    int n = blockIdx.x * blockDim.x + threadIdx.x;
    if (n >= N) return;
    float xv[NODE_F];
    *reinterpret_cast<float4*>(xv)     = *reinterpret_cast<const float4*>(x + (size_t)n * NODE_F);
    *reinterpret_cast<float4*>(xv + 4) = *reinterpret_cast<const float4*>(x + (size_t)n * NODE_F + 4);
    float pv[HID], qv[HID];
    #pragma unroll
    for (int j = 0; j < HID; j++) { pv[j] = 0.f; qv[j] = 0.f; }
    #pragma unroll
    for (int k = 0; k < NODE_F; k++) {
        float v = xv[k];
        #pragma unroll
        for (int j = 0; j < HID; j++) {
            pv[j] = fmaf(v, sA[k * HID + j], pv[j]);
            qv[j] = fmaf(v, sB[k * HID + j], qv[j]);
        }
    }
    float4* pd = reinterpret_cast<float4*>(d_p + (size_t)n * HID);
    float4* qd = reinterpret_cast<float4*>(d_q + (size_t)n * HID);
    #pragma unroll
    for (int v = 0; v < 4; v++) {
        pd[v] = reinterpret_cast<float4*>(pv)[v];
        qd[v] = reinterpret_cast<float4*>(qv)[v];
    }
}

// ---------------------------------------------------------------------------
// Edge block, 4 lanes per edge: one LDG.128 per lane covers 1/4 of p[r] (q[c]).
// Short serial chain per thread (ESTEPS=2); concurrency via many cheap blocks.
template<bool WRITE_EA, bool REDUCE>
__global__ __launch_bounds__(256)
void edge_kernel(const int* __restrict__ ei, const float* __restrict__ ea,
                 const float* __restrict__ C, const float* __restrict__ W2,
                 const float* __restrict__ b2, const float* __restrict__ ebias,
                 float* __restrict__ ea_out, int E)
{
    __shared__ float sC[2 * HID], sW2[HID * 2], sEb[HID];
    __shared__ float sred[2][8];
    int tx = threadIdx.x;
    if (tx < 32)       sC[tx] = C[tx];
    else if (tx < 64)  sW2[tx - 32] = W2[tx - 32];
    else if (tx < 80)  sEb[tx - 64] = ebias[tx - 64];
    __syncthreads();

    const float B20 = __ldg(&b2[0]);
    const float B21 = __ldg(&b2[1]);

    const int sub   = tx & 3;         // lane within edge-group
    const int group = tx >> 2;        // 0..63 within block
    const int j0    = sub * 4;        // this lane's 4 hidden units
    float acc0 = 0.f, acc1 = 0.f;

    int e = blockIdx.x * (64 * ESTEPS) + group;
    #pragma unroll
    for (int s = 0; s < ESTEPS; s++, e += 64) {
        if (e < E) {
            int r = ei[e];            // 4 lanes share the address
            int c = ei[E + e];
            float4 pv = *reinterpret_cast<const float4*>(d_p + (size_t)r * HID + j0);
            float4 qv = *reinterpret_cast<const float4*>(d_q + (size_t)c * HID + j0);
            float2 eav = *reinterpret_cast<const float2*>(ea + (size_t)e * EDGE_F);

            float o0 = 0.f, o1 = 0.f;
            float hp[4] = {pv.x, pv.y, pv.z, pv.w};
            float hq[4] = {qv.x, qv.y, qv.z, qv.w};
            #pragma unroll
            for (int k = 0; k < 4; k++) {
                float h = sEb[j0 + k] + hp[k] + hq[k];
                h = fmaf(eav.x, sC[j0 + k], h);
                h = fmaf(eav.y, sC[HID + j0 + k], h);
                h = fmaxf(h, 0.f);
                o0 = fmaf(h, sW2[2 * (j0 + k)],     o0);
                o1 = fmaf(h, sW2[2 * (j0 + k) + 1], o1);
            }
            // reduce across the 4 sub-lanes
            o0 += __shfl_xor_sync(0xffffffffu, o0, 1);
            o1 += __shfl_xor_sync(0xffffffffu, o1, 1);
            o0 += __shfl_xor_sync(0xffffffffu, o0, 2);
            o1 += __shfl_xor_sync(0xffffffffu, o1, 2);

            if (sub == 0) {
                o0 += B20; o1 += B21;
                if (WRITE_EA)
                    *reinterpret_cast<float2*>(ea_out + (size_t)e * EDGE_F) = make_float2(o0, o1);
                float* dst = &d_agg[(size_t)r * EDGE_F];
                asm volatile("red.global.add.v2.f32 [%0], {%1, %2};"
                             :: "l"(dst), "f"(o0), "f"(o1) : "memory");
                if (REDUCE) { acc0 += o0; acc1 += o1; }
            }
        }
    }

    if (REDUCE) {
        #pragma unroll
        for (int off = 16; off; off >>= 1) {
            acc0 += __shfl_down_sync(0xffffffffu, acc0, off);
            acc1 += __shfl_down_sync(0xffffffffu, acc1, off);
        }
        int warp = tx >> 5, lane = tx & 31;
        if (lane == 0) { sred[0][warp] = acc0; sred[1][warp] = acc1; }
        __syncthreads();
        if (tx == 0) {
            float t0 = 0.f, t1 = 0.f;
            #pragma unroll
            for (int w = 0; w < 8; w++) { t0 += sred[0][w]; t1 += sred[1][w]; }
            atomicAdd(&d_eacc[0], t0);
            atomicAdd(&d_eacc[1], t1);
        }
    }
}

// ---------------------------------------------------------------------------
// Node block: n_in = [g, x, agg] -> MLP(11->16 relu ->8).
// FUSE: also computes next-layer p/q per node, block-reduces node sums,
// and the LAST block runs the global MLP + folds next-layer biases.
template<bool FUSE>
__global__ __launch_bounds__(256)
void node_kernel(const float* __restrict__ x,
                 const float* __restrict__ W1,      // rows 1..10 (160 floats)
                 const float* __restrict__ nbias,
                 const float* __restrict__ W2, const float* __restrict__ b2,
                 float* __restrict__ x_out,
                 const float* __restrict__ An, const float* __restrict__ Bn,
                 const float* __restrict__ gW1, const float* __restrict__ gb1,
                 const float* __restrict__ gW2, const float* __restrict__ gb2,
                 const float* __restrict__ eW1r0n, const float* __restrict__ eb1n,
                 const float* __restrict__ nW1r0n, const float* __restrict__ nb1n,
                 float* __restrict__ ebias_out, float* __restrict__ nbias_out,
                 float invE, float invN, int N)
{
    __shared__ float sW1[10 * HID], sNb[HID], sW2n[HID * NODE_F], sB2[NODE_F];
    __shared__ float sA[NODE_F * HID], sBm[NODE_F * HID];
    __shared__ float sred[NODE_F][8];
    __shared__ bool  isLast;
    int tx = threadIdx.x;

    for (int i = tx; i < 10 * HID; i += 256) sW1[i] = W1[i];
    for (int i = tx; i < HID * NODE_F; i += 256) sW2n[i] = W2[i];
    if (tx < HID)    sNb[tx] = nbias[tx];
    if (tx < NODE_F) sB2[tx] = b2[tx];
    if (FUSE) {
        for (int i = tx; i < NODE_F * HID; i += 256) { sA[i] = An[i]; sBm[i] = Bn[i]; }
    }
    __syncthreads();

    int n = blockIdx.x * blockDim.x + tx;
    float out[NODE_F];
    #pragma unroll
    for (int k = 0; k < NODE_F; k++) out[k] = 0.f;

    if (n < N) {
        float xv[NODE_F];
        *reinterpret_cast<float4*>(xv)     = *reinterpret_cast<const float4*>(x + (size_t)n * NODE_F);
        *reinterpret_cast<float4*>(xv + 4) = *reinterpret_cast<const float4*>(x + (size_t)n * NODE_F + 4);
        float2 av = *reinterpret_cast<float2*>(&d_agg[(size_t)n * EDGE_F]);
        *reinterpret_cast<float2*>(&d_agg[(size_t)n * EDGE_F]) = make_float2(0.f, 0.f); // self-clean

        float h[HID];
        #pragma unroll
        for (int j = 0; j < HID; j++) h[j] = sNb[j];
        #pragma unroll
        for (int i = 0; i < NODE_F; i++) {
            float v = xv[i];
            #pragma unroll
            for (int j = 0; j < HID; j++) h[j] = fmaf(v, sW1[i * HID + j], h[j]);
        }
        #pragma unroll
        for (int j = 0; j < HID; j++) {
            h[j] = fmaf(av.x, sW1[8 * HID + j], h[j]);
            h[j] = fmaf(av.y, sW1[9 * HID + j], h[j]);
        }
        #pragma unroll
        for (int k = 0; k < NODE_F; k++) out[k] = sB2[k];
        #pragma unroll
        for (int j = 0; j < HID; j++) {
            float hv = fmaxf(h[j], 0.f);
            #pragma unroll
            for (int k = 0; k < NODE_F; k++)
                out[k] = fmaf(hv, sW2n[j * NODE_F + k], out[k]);
        }
        *reinterpret_cast<float4*>(x_out + (size_t)n * NODE_F)     = *reinterpret_cast<float4*>(out);
        *reinterpret_cast<float4*>(x_out + (size_t)n * NODE_F + 4) = *reinterpret_cast<float4*>(out + 4);

        if (FUSE) {   // next-layer p/q from the fresh embedding
            float pv[HID], qv[HID];
            #pragma unroll
            for (int j = 0; j < HID; j++) { pv[j] = 0.f; qv[j] = 0.f; }
            #pragma unroll
            for (int k = 0; k < NODE_F; k++) {
                float v = out[k];
                #pragma unroll
                for (int j = 0; j < HID; j++) {
                    pv[j] = fmaf(v, sA[k * HID + j], pv[j]);
                    qv[j] = fmaf(v, sBm[k * HID + j], qv[j]);
                }
            }
            float4* pd = reinterpret_cast<float4*>(d_p + (size_t)n * HID);
            float4* qd = reinterpret_cast<float4*>(d_q + (size_t)n * HID);
            #pragma unroll
            for (int v = 0; v < 4; v++) {
                pd[v] = reinterpret_cast<float4*>(pv)[v];
                qd[v] = reinterpret_cast<float4*>(qv)[v];
            }
        }
    }

    if (FUSE) {
        int warp = tx >> 5, lane = tx & 31;
        #pragma unroll
        for (int k = 0; k < NODE_F; k++) {
            float s = out[k];
            #pragma unroll
            for (int off = 16; off; off >>= 1)
                s += __shfl_down_sync(0xffffffffu, s, off);
            if (lane == 0) sred[k][warp] = s;
        }
        __syncthreads();
        if (tx < NODE_F) {
            float t = 0.f;
            #pragma unroll
            for (int w = 0; w < 8; w++) t += sred[tx][w];
            atomicAdd(&d_nacc[tx], t);
            __threadfence();
        }
        __syncthreads();
        if (tx == 0) {
            unsigned t = atomicAdd(&d_count, 1u);
            isLast = (t == gridDim.x - 1);
        }
        __syncthreads();

        if (isLast) {
            __threadfence();
            if (tx < 32) {
                float gv = d_g;
                float h = 0.f;
                if (tx < HID) {
                    h = gb1[tx];
                    #pragma unroll
                    for (int i = 0; i < NODE_F; i++)
                        h = fmaf(d_nacc[i] * invN, gW1[i * HID + tx], h);
                    h = fmaf(d_eacc[0] * invE, gW1[8 * HID + tx], h);
                    h = fmaf(d_eacc[1] * invE, gW1[9 * HID + tx], h);
                    h = fmaf(gv, gW1[10 * HID + tx], h);
                    h = fmaxf(h, 0.f) * gW2[tx];
                }
                #pragma unroll
                for (int off = 16; off; off >>= 1)
                    h += __shfl_down_sync(0xffffffffu, h, off);
                float gn = __shfl_sync(0xffffffffu, h, 0) + gb2[0];
                if (tx == 0) d_g = gn;
                if (tx < HID) {
                    ebias_out[tx] = eb1n[tx] + gn * eW1r0n[tx];
                    nbias_out[tx] = nb1n[tx] + gn * nW1r0n[tx];
                }
                if (tx < NODE_F) d_nacc[tx] = 0.f;   // self-clean
                if (tx < EDGE_F) d_eacc[tx] = 0.f;
                if (tx == 0)     d_count = 0u;
            }
        }
    }
}

// ---------------------------------------------------------------------------
extern "C" void kernel_launch(void* const* d_in, const int* in_sizes, int n_in,
                              void* d_out, int out_size)
{
    const float* x0  = (const float*)d_in[0];
    const int*   ei  = (const int*)  d_in[1];
    const float* ea0 = (const float*)d_in[2];
    const float* g0  = (const float*)d_in[3];
    const float* eW1 = (const float*)d_in[4];
    const float* eb1 = (const float*)d_in[5];
    const float* eW2 = (const float*)d_in[6];
    const float* eb2 = (const float*)d_in[7];
    const float* nW1 = (const float*)d_in[8];
    const float* nb1 = (const float*)d_in[9];
    const float* nW2 = (const float*)d_in[10];
    const float* nb2 = (const float*)d_in[11];
    const float* gW1 = (const float*)d_in[12];
    const float* gb1 = (const float*)d_in[13];
    const float* gW2 = (const float*)d_in[14];
    const float* gb2 = (const float*)d_in[15];

    const int N = in_sizes[0] / NODE_F;
    const int E = in_sizes[2] / EDGE_F;
    float* out = (float*)d_out;

    float *xA, *xB, *ea, *pEb, *pNb;
    cudaGetSymbolAddress((void**)&xA,  d_xA);
    cudaGetSymbolAddress((void**)&xB,  d_xB);
    cudaGetSymbolAddress((void**)&ea,  d_ea);
    cudaGetSymbolAddress((void**)&pEb, d_ebias);
    cudaGetSymbolAddress((void**)&pNb, d_nbias);

    const float invE = 1.0f / (float)E;
    const float invN = 1.0f / (float)N;

    const int EW1S = 19 * HID, NW1S = 11 * HID, GW1S = 11 * HID;

    pre_kernel<<<(N + 255) / 256, 256>>>(x0, eW1 + HID, eW1 + 9 * HID,
                                         g0, eW1, eb1, nW1, nb1, pEb, pNb, N);

    const float* xin[3]  = {x0, xA, xB};
    float*       xout[3] = {xA, xB, out};
    const float* eain[3] = {ea0, ea, ea};

    const int EPB = 64 * ESTEPS;
    const int eblocks = (E + EPB - 1) / EPB;
    const int nblocks = (N + 255) / 256;

    for (int l = 0; l < 3; l++) {
        const float* C    = eW1 + l * EW1S + 17 * HID;
        const float* W2e  = eW2 + l * HID * EDGE_F;
        const float* b2e  = eb2 + l * EDGE_F;
        const float* eb_l = pEb + (l & 1) * HID;

        if (l < 2)
            edge_kernel<true, true><<<eblocks, 256>>>(ei, eain[l], C, W2e, b2e, eb_l, ea, E);
        else
            edge_kernel<false, false><<<eblocks, 256>>>(ei, eain[l], C, W2e, b2e, eb_l, ea, E);

        const float* W1n  = nW1 + l * NW1S + HID;
        const float* nb_l = pNb + (l & 1) * HID;
        const float* W2n  = nW2 + l * HID * NODE_F;
        const float* b2n  = nb2 + l * NODE_F;

        if (l < 2) {
            node_kernel<true><<<nblocks, 256>>>(
                xin[l], W1n, nb_l, W2n, b2n, xout[l],
                eW1 + (l + 1) * EW1S + HID, eW1 + (l + 1) * EW1S + 9 * HID,
                gW1 + l * GW1S, gb1 + l * HID, gW2 + l * HID, gb2 + l,
                eW1 + (l + 1) * EW1S, eb1 + (l + 1) * HID,
                nW1 + (l + 1) * NW1S, nb1 + (l + 1) * HID,
                pEb + ((l + 1) & 1) * HID, pNb + ((l + 1) & 1) * HID,
                invE, invN, N);
        } else {
            node_kernel<false><<<nblocks, 256>>>(
                xin[l], W1n, nb_l, W2n, b2n, xout[l],
                nullptr, nullptr, nullptr, nullptr, nullptr, nullptr,
                nullptr, nullptr, nullptr, nullptr, nullptr, nullptr,
                invE, invN, N);
        }
    }
}

// round 6
// speedup vs baseline: 2.6431x; 1.2119x over previous
#include <cuda_runtime.h>

#define NODE_F 8
#define EDGE_F 2
#define HID 16
#define NMAX 100000
#define EMAX 1600000
#define ESTEPS 8   // edges per thread in edge kernel; block=128 → 256 edges/block

// ---- constant-memory weights (filled by async D2D memcpy each call) ----
__constant__ float c_eW1[3 * 19 * HID];  // 912
__constant__ float c_eW2[3 * HID * 2];   // 96
__constant__ float c_eb2[3 * 2];         // 6
__constant__ float c_nW1[3 * 11 * HID];  // 528
__constant__ float c_nW2[3 * HID * 8];   // 384
__constant__ float c_nb2[3 * 8];         // 24

// ---- scratch (__device__ globals per allocation-free rule) ----
__device__ alignas(16) float d_xA[NMAX * NODE_F];
__device__ alignas(16) float d_xB[NMAX * NODE_F];
__device__ alignas(16) float d_ea[EMAX * EDGE_F];
__device__ alignas(16) float d_p[NMAX * HID];     // A_l . x[n]  (64B row, line-aligned)
__device__ alignas(16) float d_q[NMAX * HID];     // B_l . x[n]
__device__ alignas(16) float d_agg[NMAX * EDGE_F];   // zero-init, self-cleaning
__device__ float d_g;
__device__ float d_eacc[EDGE_F];   // zero-init, self-cleaning
__device__ float d_nacc[NODE_F];   // zero-init, self-cleaning
__device__ float d_ebias[2][HID];  // b1_e + g*W1_e[g-row], double buffered
__device__ float d_nbias[2][HID];
__device__ unsigned d_count;       // zero-init, self-cleaning

// ---------------------------------------------------------------------------
// layer-0 p/q precompute from external x; block 0 also folds layer-0 biases.
__global__ __launch_bounds__(256)
void pre_kernel(const float* __restrict__ x,
                const float* __restrict__ g_in,
                const float* __restrict__ eb1, const float* __restrict__ nb1,
                float* __restrict__ ebias0, float* __restrict__ nbias0, int N)
{
    if (blockIdx.x == 0 && threadIdx.x < 32) {
        int t = threadIdx.x;
        float g = g_in[0];
        if (t < HID) {
            ebias0[t] = eb1[t] + g * c_eW1[t];          // edge W1 g-row (layer 0)
            nbias0[t] = nb1[t] + g * c_nW1[t];          // node W1 g-row (layer 0)
        }
        if (t == 0) d_g = g;
    }
    int n = blockIdx.x * blockDim.x + threadIdx.x;
    if (n >= N) return;
    float xv[NODE_F];
    *reinterpret_cast<float4*>(xv)     = *reinterpret_cast<const float4*>(x + (size_t)n * NODE_F);
    *reinterpret_cast<float4*>(xv + 4) = *reinterpret_cast<const float4*>(x + (size_t)n * NODE_F + 4);
    float pv[HID], qv[HID];
    #pragma unroll
    for (int j = 0; j < HID; j++) { pv[j] = 0.f; qv[j] = 0.f; }
    #pragma unroll
    for (int k = 0; k < NODE_F; k++) {
        float v = xv[k];
        #pragma unroll
        for (int j = 0; j < HID; j++) {
            pv[j] = fmaf(v, c_eW1[(1 + k) * HID + j], pv[j]);   // x[row] rows 1..8
            qv[j] = fmaf(v, c_eW1[(9 + k) * HID + j], qv[j]);   // x[col] rows 9..16
        }
    }
    float4* pd = reinterpret_cast<float4*>(d_p + (size_t)n * HID);
    float4* qd = reinterpret_cast<float4*>(d_q + (size_t)n * HID);
    #pragma unroll
    for (int v = 0; v < 4; v++) {
        pd[v] = reinterpret_cast<float4*>(pv)[v];
        qd[v] = reinterpret_cast<float4*>(qv)[v];
    }
}

// ---------------------------------------------------------------------------
// Edge block, 4 lanes per edge, weights hoisted into registers once per thread
// (amortized over ESTEPS edges). L1tex carries only gathers + scatter + streams.
template<int L, bool WRITE_EA, bool REDUCE>
__global__ __launch_bounds__(128, 10)
void edge_kernel(const int* __restrict__ ei, const float* __restrict__ ea,
                 const float* __restrict__ ebias,
                 float* __restrict__ ea_out, int E)
{
    __shared__ float sred[2][4];
    const int tx    = threadIdx.x;
    const int sub   = tx & 3;         // lane within edge-group
    const int group = tx >> 2;        // 0..31 within block
    const int j0    = sub * 4;        // this lane's 4 hidden units

    // one-time per-thread weight hoist (const port + 4 global loads)
    float c0[4], c1[4], w20[4], w21[4], ebv[4];
    #pragma unroll
    for (int k = 0; k < 4; k++) {
        c0[k]  = c_eW1[L * 304 + 17 * HID + j0 + k];
        c1[k]  = c_eW1[L * 304 + 18 * HID + j0 + k];
        w20[k] = c_eW2[L * 32 + 2 * (j0 + k)];
        w21[k] = c_eW2[L * 32 + 2 * (j0 + k) + 1];
        ebv[k] = ebias[j0 + k];
    }
    const float B20 = c_eb2[L * 2 + 0];
    const float B21 = c_eb2[L * 2 + 1];

    float acc0 = 0.f, acc1 = 0.f;
    int e = blockIdx.x * (32 * ESTEPS) + group;
    #pragma unroll
    for (int s = 0; s < ESTEPS; s++, e += 32) {
        if (e < E) {
            int r = ei[e];            // 4 lanes share the address
            int c = ei[E + e];
            float4 pv = *reinterpret_cast<const float4*>(d_p + (size_t)r * HID + j0);
            float4 qv = *reinterpret_cast<const float4*>(d_q + (size_t)c * HID + j0);
            float2 eav = *reinterpret_cast<const float2*>(ea + (size_t)e * EDGE_F);

            float o0 = 0.f, o1 = 0.f;
            float hp[4] = {pv.x, pv.y, pv.z, pv.w};
            float hq[4] = {qv.x, qv.y, qv.z, qv.w};
            #pragma unroll
            for (int k = 0; k < 4; k++) {
                float h = ebv[k] + hp[k] + hq[k];
                h = fmaf(eav.x, c0[k], h);
                h = fmaf(eav.y, c1[k], h);
                h = fmaxf(h, 0.f);
                o0 = fmaf(h, w20[k], o0);
                o1 = fmaf(h, w21[k], o1);
            }
            // reduce across the 4 sub-lanes
            o0 += __shfl_xor_sync(0xffffffffu, o0, 1);
            o1 += __shfl_xor_sync(0xffffffffu, o1, 1);
            o0 += __shfl_xor_sync(0xffffffffu, o0, 2);
            o1 += __shfl_xor_sync(0xffffffffu, o1, 2);

            if (sub == 0) {
                o0 += B20; o1 += B21;
                if (WRITE_EA)
                    *reinterpret_cast<float2*>(ea_out + (size_t)e * EDGE_F) = make_float2(o0, o1);
                float* dst = &d_agg[(size_t)r * EDGE_F];
                asm volatile("red.global.add.v2.f32 [%0], {%1, %2};"
                             :: "l"(dst), "f"(o0), "f"(o1) : "memory");
                if (REDUCE) { acc0 += o0; acc1 += o1; }
            }
        }
    }

    if (REDUCE) {
        #pragma unroll
        for (int off = 16; off; off >>= 1) {
            acc0 += __shfl_down_sync(0xffffffffu, acc0, off);
            acc1 += __shfl_down_sync(0xffffffffu, acc1, off);
        }
        int warp = tx >> 5, lane = tx & 31;
        if (lane == 0) { sred[0][warp] = acc0; sred[1][warp] = acc1; }
        __syncthreads();
        if (tx == 0) {
            float t0 = 0.f, t1 = 0.f;
            #pragma unroll
            for (int w = 0; w < 4; w++) { t0 += sred[0][w]; t1 += sred[1][w]; }
            atomicAdd(&d_eacc[0], t0);
            atomicAdd(&d_eacc[1], t1);
        }
    }
}

// ---------------------------------------------------------------------------
// Node block: weights from __constant__ with compile-time layer L (uniform port).
// FUSE: next-layer p/q, node-sum reduction, last block runs the global MLP.
template<int L, bool FUSE>
__global__ __launch_bounds__(256)
void node_kernel(const float* __restrict__ x,
                 const float* __restrict__ nbias,
                 float* __restrict__ x_out,
                 const float* __restrict__ gW1, const float* __restrict__ gb1,
                 const float* __restrict__ gW2, const float* __restrict__ gb2,
                 const float* __restrict__ eb1n, const float* __restrict__ nb1n,
                 float* __restrict__ ebias_out, float* __restrict__ nbias_out,
                 float invE, float invN, int N)
{
    __shared__ float sNb[HID];
    __shared__ float sred[NODE_F][8];
    __shared__ bool  isLast;
    int tx = threadIdx.x;
    if (tx < HID) sNb[tx] = nbias[tx];
    __syncthreads();

    int n = blockIdx.x * blockDim.x + tx;
    float out[NODE_F];
    #pragma unroll
    for (int k = 0; k < NODE_F; k++) out[k] = 0.f;

    if (n < N) {
        float xv[NODE_F];
        *reinterpret_cast<float4*>(xv)     = *reinterpret_cast<const float4*>(x + (size_t)n * NODE_F);
        *reinterpret_cast<float4*>(xv + 4) = *reinterpret_cast<const float4*>(x + (size_t)n * NODE_F + 4);
        float2 av = *reinterpret_cast<float2*>(&d_agg[(size_t)n * EDGE_F]);
        *reinterpret_cast<float2*>(&d_agg[(size_t)n * EDGE_F]) = make_float2(0.f, 0.f); // self-clean

        float h[HID];
        #pragma unroll
        for (int j = 0; j < HID; j++) h[j] = sNb[j];
        #pragma unroll
        for (int i = 0; i < NODE_F; i++) {
            float v = xv[i];
            #pragma unroll
            for (int j = 0; j < HID; j++)
                h[j] = fmaf(v, c_nW1[L * 176 + (1 + i) * HID + j], h[j]);  // x rows 1..8
        }
        #pragma unroll
        for (int j = 0; j < HID; j++) {
            h[j] = fmaf(av.x, c_nW1[L * 176 + 9 * HID + j], h[j]);
            h[j] = fmaf(av.y, c_nW1[L * 176 + 10 * HID + j], h[j]);
        }
        #pragma unroll
        for (int k = 0; k < NODE_F; k++) out[k] = c_nb2[L * 8 + k];
        #pragma unroll
        for (int j = 0; j < HID; j++) {
            float hv = fmaxf(h[j], 0.f);
            #pragma unroll
            for (int k = 0; k < NODE_F; k++)
                out[k] = fmaf(hv, c_nW2[L * 128 + j * 8 + k], out[k]);
        }
        *reinterpret_cast<float4*>(x_out + (size_t)n * NODE_F)     = *reinterpret_cast<float4*>(out);
        *reinterpret_cast<float4*>(x_out + (size_t)n * NODE_F + 4) = *reinterpret_cast<float4*>(out + 4);

        if (FUSE) {   // next-layer p/q from the fresh embedding (const weights, layer L+1)
            constexpr int EOFF = (L + 1) * 304;
            float pv[HID], qv[HID];
            #pragma unroll
            for (int j = 0; j < HID; j++) { pv[j] = 0.f; qv[j] = 0.f; }
            #pragma unroll
            for (int k = 0; k < NODE_F; k++) {
                float v = out[k];
                #pragma unroll
                for (int j = 0; j < HID; j++) {
                    pv[j] = fmaf(v, c_eW1[EOFF + (1 + k) * HID + j], pv[j]);
                    qv[j] = fmaf(v, c_eW1[EOFF + (9 + k) * HID + j], qv[j]);
                }
            }
            float4* pd = reinterpret_cast<float4*>(d_p + (size_t)n * HID);
            float4* qd = reinterpret_cast<float4*>(d_q + (size_t)n * HID);
            #pragma unroll
            for (int v = 0; v < 4; v++) {
                pd[v] = reinterpret_cast<float4*>(pv)[v];
                qd[v] = reinterpret_cast<float4*>(qv)[v];
            }
        }
    }

    if (FUSE) {
        int warp = tx >> 5, lane = tx & 31;
        #pragma unroll
        for (int k = 0; k < NODE_F; k++) {
            float s = out[k];
            #pragma unroll
            for (int off = 16; off; off >>= 1)
                s += __shfl_down_sync(0xffffffffu, s, off);
            if (lane == 0) sred[k][warp] = s;
        }
        __syncthreads();
        if (tx < NODE_F) {
            float t = 0.f;
            #pragma unroll
            for (int w = 0; w < 8; w++) t += sred[tx][w];
            atomicAdd(&d_nacc[tx], t);
            __threadfence();
        }
        __syncthreads();
        if (tx == 0) {
            unsigned t = atomicAdd(&d_count, 1u);
            isLast = (t == gridDim.x - 1);
        }
        __syncthreads();

        if (isLast) {
            __threadfence();
            if (tx < 32) {
                float gv = d_g;
                float h = 0.f;
                if (tx < HID) {
                    h = gb1[tx];
                    #pragma unroll
                    for (int i = 0; i < NODE_F; i++)
                        h = fmaf(d_nacc[i] * invN, gW1[i * HID + tx], h);
                    h = fmaf(d_eacc[0] * invE, gW1[8 * HID + tx], h);
                    h = fmaf(d_eacc[1] * invE, gW1[9 * HID + tx], h);
                    h = fmaf(gv, gW1[10 * HID + tx], h);
                    h = fmaxf(h, 0.f) * gW2[tx];
                }
                #pragma unroll
                for (int off = 16; off; off >>= 1)
                    h += __shfl_down_sync(0xffffffffu, h, off);
                float gn = __shfl_sync(0xffffffffu, h, 0) + gb2[0];
                if (tx == 0) d_g = gn;
                if (tx < HID) {
                    ebias_out[tx] = eb1n[tx] + gn * c_eW1[(L + 1) * 304 + tx];
                    nbias_out[tx] = nb1n[tx] + gn * c_nW1[(L + 1) * 176 + tx];
                }
                if (tx < NODE_F) d_nacc[tx] = 0.f;   // self-clean
                if (tx < EDGE_F) d_eacc[tx] = 0.f;
                if (tx == 0)     d_count = 0u;
            }
        }
    }
}

// ---------------------------------------------------------------------------
extern "C" void kernel_launch(void* const* d_in, const int* in_sizes, int n_in,
                              void* d_out, int out_size)
{
    const float* x0  = (const float*)d_in[0];
    const int*   ei  = (const int*)  d_in[1];
    const float* ea0 = (const float*)d_in[2];
    const float* g0  = (const float*)d_in[3];
    const float* eW1 = (const float*)d_in[4];
    const float* eb1 = (const float*)d_in[5];
    const float* eW2 = (const float*)d_in[6];
    const float* eb2 = (const float*)d_in[7];
    const float* nW1 = (const float*)d_in[8];
    const float* nb1 = (const float*)d_in[9];
    const float* nW2 = (const float*)d_in[10];
    const float* nb2 = (const float*)d_in[11];
    const float* gW1 = (const float*)d_in[12];
    const float* gb1 = (const float*)d_in[13];
    const float* gW2 = (const float*)d_in[14];
    const float* gb2 = (const float*)d_in[15];

    const int N = in_sizes[0] / NODE_F;
    const int E = in_sizes[2] / EDGE_F;
    float* out = (float*)d_out;

    // stage weights into constant memory (D2D, graph-capturable)
    cudaMemcpyToSymbolAsync(c_eW1, eW1, 912 * sizeof(float), 0, cudaMemcpyDeviceToDevice, 0);
    cudaMemcpyToSymbolAsync(c_eW2, eW2,  96 * sizeof(float), 0, cudaMemcpyDeviceToDevice, 0);
    cudaMemcpyToSymbolAsync(c_eb2, eb2,   6 * sizeof(float), 0, cudaMemcpyDeviceToDevice, 0);
    cudaMemcpyToSymbolAsync(c_nW1, nW1, 528 * sizeof(float), 0, cudaMemcpyDeviceToDevice, 0);
    cudaMemcpyToSymbolAsync(c_nW2, nW2, 384 * sizeof(float), 0, cudaMemcpyDeviceToDevice, 0);
    cudaMemcpyToSymbolAsync(c_nb2, nb2,  24 * sizeof(float), 0, cudaMemcpyDeviceToDevice, 0);

    float *xA, *xB, *ea, *pEb, *pNb;
    cudaGetSymbolAddress((void**)&xA,  d_xA);
    cudaGetSymbolAddress((void**)&xB,  d_xB);
    cudaGetSymbolAddress((void**)&ea,  d_ea);
    cudaGetSymbolAddress((void**)&pEb, d_ebias);
    cudaGetSymbolAddress((void**)&pNb, d_nbias);

    const float invE = 1.0f / (float)E;
    const float invN = 1.0f / (float)N;
    const int GW1S = 11 * HID;

    pre_kernel<<<(N + 255) / 256, 256>>>(x0, g0, eb1, nb1, pEb, pNb, N);

    const int EPB = 32 * ESTEPS;                 // 256 edges / 128-thread block
    const int eblocks = (E + EPB - 1) / EPB;
    const int nblocks = (N + 255) / 256;

    // ---- layer 0 ----
    edge_kernel<0, true, true><<<eblocks, 128>>>(ei, ea0, pEb + 0 * HID, ea, E);
    node_kernel<0, true><<<nblocks, 256>>>(
        x0, pNb + 0 * HID, xA,
        gW1 + 0 * GW1S, gb1 + 0 * HID, gW2 + 0 * HID, gb2 + 0,
        eb1 + 1 * HID, nb1 + 1 * HID,
        pEb + 1 * HID, pNb + 1 * HID, invE, invN, N);

    // ---- layer 1 ----
    edge_kernel<1, true, true><<<eblocks, 128>>>(ei, ea, pEb + 1 * HID, ea, E);
    node_kernel<1, true><<<nblocks, 256>>>(
        xA, pNb + 1 * HID, xB,
        gW1 + 1 * GW1S, gb1 + 1 * HID, gW2 + 1 * HID, gb2 + 1,
        eb1 + 2 * HID, nb1 + 2 * HID,
        pEb + 0 * HID, pNb + 0 * HID, invE, invN, N);

    // ---- layer 2 (no ea_out, no global block needed) ----
    edge_kernel<2, false, false><<<eblocks, 128>>>(ei, ea, pEb + 0 * HID, ea, E);
    node_kernel<2, false><<<nblocks, 256>>>(
        xB, pNb + 0 * HID, out,
        nullptr, nullptr, nullptr, nullptr,
        nullptr, nullptr, nullptr, nullptr, invE, invN, N);
}